// round 2
// baseline (speedup 1.0000x reference)
#include <cuda_runtime.h>
#include <cuda_bf16.h>
#include <cstdint>

#define NB   64      // batch
#define TT   64      // seq len
#define NN   1024    // items
#define SS   32      // state dim
#define DD   32      // item dim
#define FF   64      // feature = SS + DD
#define GG   96      // 3 * SS
#define MAXDEG 96
#define BN   (NB * NN)

// Persistent state (module globals — no runtime allocation)
__device__ float g_h[BN * SS];        // (row, s) row-major
__device__ float g_Gi[GG * BN];       // TRANSPOSED: (g, row) for coalesced reads in GRU
__device__ int   g_csc[NN * MAXDEG];  // in-neighbors of each v (sorted by u)
__device__ int   g_deg[NN];
__device__ float g_Cn[NN * DD];       // adj^T @ item_emb

__device__ __forceinline__ float sigmf(float x) {
    return 1.0f / (1.0f + __expf(-x));
}
__device__ __forceinline__ float tanhfast(float x) {
    float e = __expf(-2.0f * x);
    return (1.0f - e) / (1.0f + e);
}

// ---------------------------------------------------------------------------
// Build CSC: for each v, ordered list of u with adj[u][v] != 0
// ---------------------------------------------------------------------------
__global__ void build_csc_kernel(const float* __restrict__ adj) {
    int v = blockIdx.x;
    int t = threadIdx.x;          // 256 threads, each handles 4 u's
    __shared__ int cnt[256];

    int base = t * 4;
    int flags = 0, c = 0;
    #pragma unroll
    for (int i = 0; i < 4; i++) {
        float a = adj[(base + i) * NN + v];
        if (a != 0.0f) { c++; flags |= (1 << i); }
    }
    cnt[t] = c;
    __syncthreads();
    // Hillis-Steele inclusive scan
    for (int st = 1; st < 256; st <<= 1) {
        int val = cnt[t];
        int add = (t >= st) ? cnt[t - st] : 0;
        __syncthreads();
        cnt[t] = val + add;
        __syncthreads();
    }
    int off = cnt[t] - c;   // exclusive prefix
    int total = cnt[255];
    int w = 0;
    #pragma unroll
    for (int i = 0; i < 4; i++) {
        if (flags & (1 << i)) {
            int idx = off + w;
            if (idx < MAXDEG) g_csc[v * MAXDEG + idx] = base + i;
            w++;
        }
    }
    if (t == 0) g_deg[v] = (total < MAXDEG) ? total : MAXDEG;
}

// ---------------------------------------------------------------------------
// Cn[v][d] = sum over in-neighbors u of item_emb[u][d]
// ---------------------------------------------------------------------------
__global__ void build_cn_kernel(const float* __restrict__ item_emb) {
    int v = blockIdx.x;
    int d = threadIdx.x;          // 32 threads
    int deg = g_deg[v];
    float s = 0.0f;
    for (int k = 0; k < deg; k++) {
        int u = g_csc[v * MAXDEG + k];
        s += item_emb[u * DD + d];
    }
    g_Cn[v * DD + d] = s;
}

// ---------------------------------------------------------------------------
// Init: h = 0, Gi[g][r] = b_ih[g]  (since m = 0)
// ---------------------------------------------------------------------------
__global__ void init_state_kernel(const float* __restrict__ b_ih) {
    int i = blockIdx.x * blockDim.x + threadIdx.x;
    if (i < GG * BN) g_Gi[i] = b_ih[i / BN];
    if (i < BN * SS) g_h[i] = 0.0f;
}

// ---------------------------------------------------------------------------
// Kernel A (per step): sparse update at neigh nodes.
// Grid: (MAXDEG, NB); block 128 threads. Each block = one (b, v) pair.
// Computes dst_fea at v and writes the refreshed Gi row (transposed layout).
// ---------------------------------------------------------------------------
__global__ void step_sparse_kernel(
    const int* __restrict__ item_ids, const int* __restrict__ responses, int t,
    const float* __restrict__ adj,
    const float* __restrict__ item_emb, const float* __restrict__ resp_emb,
    const float* __restrict__ w_in, const float* __restrict__ b_in,
    const float* __restrict__ w_out, const float* __restrict__ b_out,
    const float* __restrict__ in_a, const float* __restrict__ out_a,
    const float* __restrict__ w_ih, const float* __restrict__ b_ih)
{
    int b = blockIdx.y;
    int j = blockIdx.x;
    int item = item_ids[b * TT + t];
    if (j >= g_deg[item]) return;
    int v = g_csc[item * MAXDEG + j];
    int resp = responses[b * TT + t];

    __shared__ float fea[128];
    __shared__ float tin[64];
    __shared__ float tout[64];
    __shared__ float dst[64];
    __shared__ float part[4][32];

    int tid = threadIdx.x;
    int lane = tid & 31;
    int w = tid >> 5;

    // --- src_fea[0:32] = sum over in-neighbors u of h[b,u,:] ---
    const float* hb = g_h + (size_t)b * NN * SS;
    int degv = g_deg[v];
    const int* nbr = &g_csc[v * MAXDEG];
    float s = 0.0f;
    for (int k = w; k < degv; k += 4) {
        int u = nbr[k];
        s += hb[u * SS + lane];
    }
    part[w][lane] = s;
    __syncthreads();

    if (tid < 32) {
        int d = tid;
        fea[64 + d] = part[0][d] + part[1][d] + part[2][d] + part[3][d];
        // h part
        fea[d] = hb[v * SS + d];
        // merged at v
        float re = resp_emb[resp * DD + d];
        fea[32 + d] = (v == item) ? re : item_emb[v * DD + d];
        // src_fea[32:64] = Cn[v] + adj[item,v] * (resp_emb - item_emb[item])
        float corr = (adj[(size_t)item * NN + v] != 0.0f)
                         ? (re - item_emb[item * DD + d]) : 0.0f;
        fea[96 + d] = g_Cn[v * DD + d] + corr;
    }
    __syncthreads();

    // --- in_fea / out_fea: 128 outputs, 128-dot each ---
    {
        const float* wrow;
        float bias;
        int o;
        if (tid < 64) { o = tid;      wrow = w_in  + o * 128; bias = b_in[o]; }
        else          { o = tid - 64; wrow = w_out + o * 128; bias = b_out[o]; }
        float acc = bias;
        #pragma unroll
        for (int k = 0; k < 128; k += 4) {
            float4 wv = *reinterpret_cast<const float4*>(wrow + k);
            acc += wv.x * fea[k] + wv.y * fea[k + 1]
                 + wv.z * fea[k + 2] + wv.w * fea[k + 3];
        }
        if (tid < 64) tin[o] = acc; else tout[o] = acc;
    }
    __syncthreads();

    if (tid < 64) {
        dst[tid] = out_a[v] * tout[tid] + in_a[v] * tin[tid];
    }
    __syncthreads();

    // --- refresh Gi row: Gi[g][row] = b_ih[g] + w_ih[g,:] . dst ---
    if (tid < GG) {
        int g = tid;
        float acc = b_ih[g];
        const float* wrow = w_ih + g * FF;
        #pragma unroll
        for (int k = 0; k < FF; k += 4) {
            float4 wv = *reinterpret_cast<const float4*>(wrow + k);
            acc += wv.x * dst[k] + wv.y * dst[k + 1]
                 + wv.z * dst[k + 2] + wv.w * dst[k + 3];
        }
        g_Gi[(size_t)g * BN + b * NN + v] = acc;
    }
}

// ---------------------------------------------------------------------------
// Kernel B (per step): dense GRU over all B*N rows + fc output.
// Grid: BN/256 blocks x 256 threads; one thread = one row.
// ---------------------------------------------------------------------------
__global__ void step_gru_kernel(
    const float* __restrict__ w_hh, const float* __restrict__ b_hh,
    const float* __restrict__ w_fc, const float* __restrict__ b_fc,
    float* __restrict__ out, int t, float* __restrict__ h_final)
{
    __shared__ float whh[GG * SS];
    __shared__ float bhh[GG];
    __shared__ float wfc[SS];

    int tid = threadIdx.x;
    for (int i = tid; i < GG * SS; i += 256) whh[i] = w_hh[i];
    if (tid < GG) bhh[tid] = b_hh[tid];
    if (tid < SS) wfc[tid] = w_fc[tid];
    __syncthreads();

    int r = blockIdx.x * 256 + tid;

    // load h row
    float h[SS];
    {
        const float4* hp = reinterpret_cast<const float4*>(g_h + (size_t)r * SS);
        #pragma unroll
        for (int q = 0; q < SS / 4; q++) {
            float4 hv = hp[q];
            h[q * 4 + 0] = hv.x; h[q * 4 + 1] = hv.y;
            h[q * 4 + 2] = hv.z; h[q * 4 + 3] = hv.w;
        }
    }

    // r gate
    float rg[SS];
    #pragma unroll
    for (int d = 0; d < SS; d++) {
        float acc = bhh[d];
        #pragma unroll
        for (int k = 0; k < SS; k++) acc += whh[d * SS + k] * h[k];
        float gi = g_Gi[(size_t)d * BN + r];
        rg[d] = sigmf(gi + acc);
    }

    // z, n, h_new, fc
    float hnew[SS];
    float fc = 0.0f;
    #pragma unroll
    for (int d = 0; d < SS; d++) {
        float accz = bhh[SS + d];
        float accn = bhh[2 * SS + d];
        #pragma unroll
        for (int k = 0; k < SS; k++) {
            float hk = h[k];
            accz += whh[(SS + d) * SS + k] * hk;
            accn += whh[(2 * SS + d) * SS + k] * hk;
        }
        float z = sigmf(g_Gi[(size_t)(SS + d) * BN + r] + accz);
        float n = tanhfast(g_Gi[(size_t)(2 * SS + d) * BN + r] + rg[d] * accn);
        float hn = (1.0f - z) * n + z * h[d];
        hnew[d] = hn;
        fc += hn * wfc[d];
    }

    int b = r >> 10;
    int v = r & (NN - 1);
    out[((size_t)b * TT + t) * NN + v] = sigmf(fc + b_fc[0]);

    // store new h
    {
        float4* hp = reinterpret_cast<float4*>(g_h + (size_t)r * SS);
        #pragma unroll
        for (int q = 0; q < SS / 4; q++) {
            float4 hv;
            hv.x = hnew[q * 4 + 0]; hv.y = hnew[q * 4 + 1];
            hv.z = hnew[q * 4 + 2]; hv.w = hnew[q * 4 + 3];
            hp[q] = hv;
            if (h_final) {
                reinterpret_cast<float4*>(h_final + (size_t)r * SS)[q] = hv;
            }
        }
    }
}

// ---------------------------------------------------------------------------
extern "C" void kernel_launch(void* const* d_in, const int* in_sizes, int n_in,
                              void* d_out, int out_size) {
    const int*   item_ids  = (const int*)  d_in[0];
    const int*   responses = (const int*)  d_in[1];
    const float* adj       = (const float*)d_in[2];
    const float* item_emb  = (const float*)d_in[3];
    const float* resp_emb  = (const float*)d_in[4];
    const float* w_in      = (const float*)d_in[5];
    const float* b_in      = (const float*)d_in[6];
    const float* w_out     = (const float*)d_in[7];
    const float* b_out     = (const float*)d_in[8];
    const float* in_a      = (const float*)d_in[9];
    const float* out_a     = (const float*)d_in[10];
    const float* w_ih      = (const float*)d_in[11];
    const float* w_hh      = (const float*)d_in[12];
    const float* b_ih      = (const float*)d_in[13];
    const float* b_hh      = (const float*)d_in[14];
    const float* w_fc      = (const float*)d_in[15];
    const float* b_fc      = (const float*)d_in[16];

    float* out    = (float*)d_out;                       // (B, T, N)
    float* h_out  = out + (size_t)NB * TT * NN;          // (B, N, S)

    build_csc_kernel<<<NN, 256>>>(adj);
    build_cn_kernel<<<NN, 32>>>(item_emb);
    {
        int total = GG * BN;
        init_state_kernel<<<(total + 255) / 256, 256>>>(b_ih);
    }

    for (int t = 0; t < TT; t++) {
        step_sparse_kernel<<<dim3(MAXDEG, NB), 128>>>(
            item_ids, responses, t, adj, item_emb, resp_emb,
            w_in, b_in, w_out, b_out, in_a, out_a, w_ih, b_ih);
        step_gru_kernel<<<BN / 256, 256>>>(
            w_hh, b_hh, w_fc, b_fc, out, t,
            (t == TT - 1) ? h_out : nullptr);
    }
}

// round 3
// speedup vs baseline: 1.0609x; 1.0609x over previous
#include <cuda_runtime.h>
#include <cuda_bf16.h>
#include <cstdint>

#define NB   64      // batch
#define TT   64      // seq len
#define NN   1024    // items
#define SS   32      // state dim
#define DD   32      // item dim
#define FF   64      // feature = SS + DD
#define GG   96      // 3 * SS
#define MAXDEG 96
#define BN   (NB * NN)

// Persistent state (module globals — no runtime allocation)
__device__ float g_h[BN * SS];          // (row, s) row-major
__device__ float g_Gi[GG * BN];         // TRANSPOSED: (g, row)
__device__ int   g_csc[NN * MAXDEG];    // in-neighbors of each v (zero-padded)
__device__ int   g_deg[NN];
__device__ float g_Cn[NN * DD];         // adj^T @ item_emb
// Folded weights
__device__ float g_M[192 * 128];        // [w_ih@w_in ; w_ih@w_out], original order
__device__ float g_MX_T[64 * 192];      // transposed, permuted-g: cols {h, agg}
__device__ float g_MC_T[64 * 192];      // transposed, permuted-g: rows 0-31 merged cols, 32-63 Cn cols
__device__ float g_Pc[NN * 192];        // per-node constant (permuted-g) incl. bias fold

__device__ __forceinline__ float sigmf(float x) {
    return 1.0f / (1.0f + __expf(-x));
}
__device__ __forceinline__ float tanhfast(float x) {
    float e = __expf(-2.0f * x);
    return (1.0f - e) / (1.0f + e);
}
__device__ __forceinline__ unsigned long long pack2(float lo, float hi) {
    unsigned long long r;
    asm("mov.b64 %0, {%1, %2};" : "=l"(r) : "f"(lo), "f"(hi));
    return r;
}
__device__ __forceinline__ void unpack2(unsigned long long v, float& lo, float& hi) {
    asm("mov.b64 {%0, %1}, %2;" : "=f"(lo), "=f"(hi) : "l"(v));
}
__device__ __forceinline__ unsigned long long ffma2(unsigned long long a,
                                                    unsigned long long b,
                                                    unsigned long long c) {
    unsigned long long d;
    asm("fma.rn.f32x2 %0, %1, %2, %3;" : "=l"(d) : "l"(a), "l"(b), "l"(c));
    return d;
}

// permuted g position: [in 0:48 | out 0:48 | in 48:96 | out 48:96]
__device__ __forceinline__ int gpos(int gg, int is_out) {
    return (gg / 48) * 96 + (is_out ? 48 : 0) + (gg % 48);
}

// ---------------------------------------------------------------------------
// Build CSC (zero-padded to MAXDEG)
// ---------------------------------------------------------------------------
__global__ void build_csc_kernel(const float* __restrict__ adj) {
    int v = blockIdx.x;
    int t = threadIdx.x;          // 256 threads, each handles 4 u's
    __shared__ int cnt[256];

    int base = t * 4;
    int flags = 0, c = 0;
    #pragma unroll
    for (int i = 0; i < 4; i++) {
        float a = adj[(base + i) * NN + v];
        if (a != 0.0f) { c++; flags |= (1 << i); }
    }
    cnt[t] = c;
    __syncthreads();
    for (int st = 1; st < 256; st <<= 1) {
        int val = cnt[t];
        int add = (t >= st) ? cnt[t - st] : 0;
        __syncthreads();
        cnt[t] = val + add;
        __syncthreads();
    }
    int off = cnt[t] - c;
    int total = cnt[255];
    int w = 0;
    #pragma unroll
    for (int i = 0; i < 4; i++) {
        if (flags & (1 << i)) {
            int idx = off + w;
            if (idx < MAXDEG) g_csc[v * MAXDEG + idx] = base + i;
            w++;
        }
    }
    int tot = (total < MAXDEG) ? total : MAXDEG;
    if (t == 0) g_deg[v] = tot;
    // zero-pad
    for (int p = tot + t; p < MAXDEG; p += 256) g_csc[v * MAXDEG + p] = 0;
}

__global__ void build_cn_kernel(const float* __restrict__ item_emb) {
    int v = blockIdx.x;
    int d = threadIdx.x;
    int deg = g_deg[v];
    float s = 0.0f;
    for (int k = 0; k < deg; k++) {
        int u = g_csc[v * MAXDEG + k];
        s += item_emb[u * DD + d];
    }
    g_Cn[v * DD + d] = s;
}

// ---------------------------------------------------------------------------
// M = [w_ih @ w_in ; w_ih @ w_out]  (192 x 128) + transposed/permuted slices
// ---------------------------------------------------------------------------
__global__ void build_M_kernel(const float* __restrict__ w_ih,
                               const float* __restrict__ w_in,
                               const float* __restrict__ w_out) {
    int idx = blockIdx.x;          // 0..191
    int k = threadIdx.x;           // 0..127
    int is_out = idx >= 96;
    int gg = idx % 96;
    int pos = gpos(gg, is_out);
    const float* wio = is_out ? w_out : w_in;
    float acc = 0.0f;
    #pragma unroll 8
    for (int o = 0; o < FF; o++) acc += w_ih[gg * FF + o] * wio[o * 128 + k];
    g_M[idx * 128 + k] = acc;
    if (k < 32)                 g_MX_T[k * 192 + pos] = acc;          // h cols
    else if (k >= 64 && k < 96) g_MX_T[(k - 32) * 192 + pos] = acc;   // agg cols
    else if (k >= 32 && k < 64) g_MC_T[(k - 32) * 192 + pos] = acc;   // merged cols
    else                        g_MC_T[(k - 96 + 32) * 192 + pos] = acc; // Cn cols
}

// Pc[v][pos] = M[:,32:64]@item_emb[v] + M[:,96:128]@Cn[v] + w_ih@bias
__global__ void build_Pc_kernel(const float* __restrict__ item_emb,
                                const float* __restrict__ w_ih,
                                const float* __restrict__ b_in,
                                const float* __restrict__ b_out) {
    int v = blockIdx.x;
    int idx = threadIdx.x;   // 0..191
    int is_out = idx >= 96;
    int gg = idx % 96;
    int pos = gpos(gg, is_out);
    __shared__ float ie[32], cn[32];
    if (idx < 32) ie[idx] = item_emb[v * DD + idx];
    else if (idx < 64) cn[idx - 32] = g_Cn[v * DD + (idx - 32)];
    __syncthreads();
    const float* bio = is_out ? b_out : b_in;
    float acc = 0.0f;
    #pragma unroll 8
    for (int o = 0; o < FF; o++) acc += w_ih[gg * FF + o] * bio[o];
    #pragma unroll
    for (int k = 0; k < 32; k++)
        acc += g_M[idx * 128 + 32 + k] * ie[k] + g_M[idx * 128 + 96 + k] * cn[k];
    g_Pc[v * 192 + pos] = acc;
}

__global__ void init_state_kernel(const float* __restrict__ b_ih) {
    int i = blockIdx.x * blockDim.x + threadIdx.x;
    if (i < GG * BN) g_Gi[i] = b_ih[i / BN];
    if (i < BN * SS) g_h[i] = 0.0f;
}

// ---------------------------------------------------------------------------
// Kernel A2: sparse Gi refresh.  grid (2, NB), 256 threads, warp-per-node.
// ---------------------------------------------------------------------------
__global__ void __launch_bounds__(256) step_sparse2(
    const int* __restrict__ item_ids, const int* __restrict__ responses, int t,
    const float* __restrict__ adj,
    const float* __restrict__ item_emb, const float* __restrict__ resp_emb,
    const float* __restrict__ in_a, const float* __restrict__ out_a,
    const float* __restrict__ b_ih)
{
    __shared__ float MXs[64 * 96];
    __shared__ float qS[96], qX[96];
    __shared__ float sdvec[32];
    __shared__ float xbuf[8][64];
    __shared__ float tbuf[8][96];

    int b = blockIdx.y, half = blockIdx.x;
    int tid = threadIdx.x, lane = tid & 31, w = tid >> 5;
    int item = item_ids[b * TT + t];
    int resp = responses[b * TT + t];
    int deg = g_deg[item];

    for (int i = tid; i < 64 * 96; i += 256) {
        int k = i / 96, o = i - k * 96;
        MXs[i] = g_MX_T[k * 192 + half * 96 + o];
    }
    if (tid < 32) sdvec[tid] = resp_emb[resp * DD + tid] - item_emb[item * DD + tid];
    __syncthreads();
    if (tid < 192) {
        int o = tid % 96;
        int isX = tid >= 96;
        const float* base = g_MC_T + (isX ? 32 * 192 : 0) + half * 96 + o;
        float acc = 0.0f;
        #pragma unroll
        for (int k = 0; k < 32; k++) acc += base[k * 192] * sdvec[k];
        if (isX) qX[o] = acc; else qS[o] = acc;
    }
    __syncthreads();

    const float* hb = g_h + (size_t)b * NN * SS;
    for (int j = w; j < deg; j += 8) {
        int v = g_csc[item * MAXDEG + j];
        // ---- gather agg = sum of in-neighbor h rows (unroll-8, MLP 8) ----
        float agg = 0.0f;
        int degv = g_deg[v];
        const int* nb = g_csc + v * MAXDEG;
        for (int k = 0; k < degv; k += 8) {
            #pragma unroll
            for (int i = 0; i < 8; i++) {
                int u = nb[k + i];
                float val = hb[u * SS + lane];
                if (k + i < degv) agg += val;
            }
        }
        xbuf[w][lane] = hb[v * SS + lane];
        xbuf[w][32 + lane] = agg;
        __syncwarp();

        bool hasrev = adj[(size_t)item * NN + v] != 0.0f;
        bool isself = (v == item);
        float a0 = g_Pc[v * 192 + half * 96 + lane];
        float a1 = g_Pc[v * 192 + half * 96 + 32 + lane];
        float a2 = g_Pc[v * 192 + half * 96 + 64 + lane];
        if (hasrev) { a0 += qX[lane]; a1 += qX[32 + lane]; a2 += qX[64 + lane]; }
        if (isself) { a0 += qS[lane]; a1 += qS[32 + lane]; a2 += qS[64 + lane]; }
        #pragma unroll
        for (int k = 0; k < 64; k++) {
            float xk = xbuf[w][k];
            a0 += MXs[k * 96 + lane]      * xk;
            a1 += MXs[k * 96 + 32 + lane] * xk;
            a2 += MXs[k * 96 + 64 + lane] * xk;
        }
        tbuf[w][lane] = a0;
        tbuf[w][32 + lane] = a1;
        tbuf[w][64 + lane] = a2;
        __syncwarp();

        float ia = in_a[v], oa = out_a[v];
        {
            int i = lane;                 // 0..31 (<48)
            int gg = half * 48 + i;
            float gi = b_ih[gg] + ia * tbuf[w][i] + oa * tbuf[w][48 + i];
            g_Gi[(size_t)gg * BN + b * NN + v] = gi;
        }
        if (lane < 16) {
            int i = 32 + lane;            // 32..47
            int gg = half * 48 + i;
            float gi = b_ih[gg] + ia * tbuf[w][i] + oa * tbuf[w][48 + i];
            g_Gi[(size_t)gg * BN + b * NN + v] = gi;
        }
        __syncwarp();
    }
}

// ---------------------------------------------------------------------------
// Kernel B2: packed-f32x2 GRU, 2 rows per thread. grid 128 x 256.
// ---------------------------------------------------------------------------
__global__ void __launch_bounds__(256, 1) step_gru2(
    const float* __restrict__ w_hh, const float* __restrict__ b_hh,
    const float* __restrict__ w_fc, const float* __restrict__ b_fc,
    float* __restrict__ out, int t, float* __restrict__ h_final)
{
    __shared__ unsigned long long whh2[GG * SS];   // {w,w} duplicated
    __shared__ float bhh[GG];
    __shared__ float wfc[SS];

    int tid = threadIdx.x;
    for (int i = tid; i < GG * SS; i += 256) {
        float wv = w_hh[i];
        whh2[i] = pack2(wv, wv);
    }
    if (tid < GG) bhh[tid] = b_hh[tid];
    if (tid < SS) wfc[tid] = w_fc[tid];
    __syncthreads();

    int i = blockIdx.x * 256 + tid;       // pair index 0..BN/2-1
    int r0 = 2 * i;

    unsigned long long hp[SS];
    {
        const float4* p0 = reinterpret_cast<const float4*>(g_h + (size_t)r0 * SS);
        const float4* p1 = reinterpret_cast<const float4*>(g_h + (size_t)(r0 + 1) * SS);
        #pragma unroll
        for (int q = 0; q < 8; q++) {
            float4 a = p0[q];
            float4 c = p1[q];
            hp[q * 4 + 0] = pack2(a.x, c.x);
            hp[q * 4 + 1] = pack2(a.y, c.y);
            hp[q * 4 + 2] = pack2(a.z, c.z);
            hp[q * 4 + 3] = pack2(a.w, c.w);
        }
    }

    const unsigned long long* gip = reinterpret_cast<const unsigned long long*>(g_Gi);

    float hn0[SS], hn1[SS];
    float fc0 = 0.0f, fc1 = 0.0f;

    #pragma unroll 2
    for (int d = 0; d < SS; d++) {
        unsigned long long ar = 0ull, az = 0ull, an = 0ull;  // (0.0f, 0.0f)
        #pragma unroll
        for (int k = 0; k < SS; k++) {
            unsigned long long h2 = hp[k];
            ar = ffma2(whh2[d * SS + k], h2, ar);
            az = ffma2(whh2[(SS + d) * SS + k], h2, az);
            an = ffma2(whh2[(2 * SS + d) * SS + k], h2, an);
        }
        unsigned long long gr = gip[(size_t)d * (BN / 2) + i];
        unsigned long long gz = gip[(size_t)(SS + d) * (BN / 2) + i];
        unsigned long long gn = gip[(size_t)(2 * SS + d) * (BN / 2) + i];
        float arl, arh, azl, azh, anl, anh;
        float grl, grh, gzl, gzh, gnl, gnh, hl, hh;
        unpack2(ar, arl, arh);  unpack2(az, azl, azh);  unpack2(an, anl, anh);
        unpack2(gr, grl, grh);  unpack2(gz, gzl, gzh);  unpack2(gn, gnl, gnh);
        unpack2(hp[d], hl, hh);
        float br = bhh[d], bz = bhh[SS + d], bn = bhh[2 * SS + d];

        float r_l = sigmf(arl + br + grl);
        float r_h = sigmf(arh + br + grh);
        float z_l = sigmf(azl + bz + gzl);
        float z_h = sigmf(azh + bz + gzh);
        float n_l = tanhfast(gnl + r_l * (anl + bn));
        float n_h = tanhfast(gnh + r_h * (anh + bn));
        float h_l = (1.0f - z_l) * n_l + z_l * hl;
        float h_h = (1.0f - z_h) * n_h + z_h * hh;
        hn0[d] = h_l;
        hn1[d] = h_h;
        fc0 += h_l * wfc[d];
        fc1 += h_h * wfc[d];
    }

    int b0 = r0 >> 10;
    int v0 = r0 & (NN - 1);
    float bf = b_fc[0];
    out[((size_t)b0 * TT + t) * NN + v0]     = sigmf(fc0 + bf);
    out[((size_t)b0 * TT + t) * NN + v0 + 1] = sigmf(fc1 + bf);

    {
        float4* p0 = reinterpret_cast<float4*>(g_h + (size_t)r0 * SS);
        float4* p1 = reinterpret_cast<float4*>(g_h + (size_t)(r0 + 1) * SS);
        #pragma unroll
        for (int q = 0; q < 8; q++) {
            float4 a, c;
            a.x = hn0[q * 4 + 0]; a.y = hn0[q * 4 + 1];
            a.z = hn0[q * 4 + 2]; a.w = hn0[q * 4 + 3];
            c.x = hn1[q * 4 + 0]; c.y = hn1[q * 4 + 1];
            c.z = hn1[q * 4 + 2]; c.w = hn1[q * 4 + 3];
            p0[q] = a;
            p1[q] = c;
            if (h_final) {
                reinterpret_cast<float4*>(h_final + (size_t)r0 * SS)[q] = a;
                reinterpret_cast<float4*>(h_final + (size_t)(r0 + 1) * SS)[q] = c;
            }
        }
    }
}

// ---------------------------------------------------------------------------
extern "C" void kernel_launch(void* const* d_in, const int* in_sizes, int n_in,
                              void* d_out, int out_size) {
    const int*   item_ids  = (const int*)  d_in[0];
    const int*   responses = (const int*)  d_in[1];
    const float* adj       = (const float*)d_in[2];
    const float* item_emb  = (const float*)d_in[3];
    const float* resp_emb  = (const float*)d_in[4];
    const float* w_in      = (const float*)d_in[5];
    const float* b_in      = (const float*)d_in[6];
    const float* w_out     = (const float*)d_in[7];
    const float* b_out     = (const float*)d_in[8];
    const float* in_a      = (const float*)d_in[9];
    const float* out_a     = (const float*)d_in[10];
    const float* w_ih      = (const float*)d_in[11];
    const float* w_hh      = (const float*)d_in[12];
    const float* b_ih      = (const float*)d_in[13];
    const float* b_hh      = (const float*)d_in[14];
    const float* w_fc      = (const float*)d_in[15];
    const float* b_fc      = (const float*)d_in[16];

    float* out    = (float*)d_out;                       // (B, T, N)
    float* h_out  = out + (size_t)NB * TT * NN;          // (B, N, S)

    build_csc_kernel<<<NN, 256>>>(adj);
    build_cn_kernel<<<NN, 32>>>(item_emb);
    build_M_kernel<<<192, 128>>>(w_ih, w_in, w_out);
    build_Pc_kernel<<<NN, 192>>>(item_emb, w_ih, b_in, b_out);
    {
        int total = GG * BN;
        init_state_kernel<<<(total + 255) / 256, 256>>>(b_ih);
    }

    for (int t = 0; t < TT; t++) {
        step_sparse2<<<dim3(2, NB), 256>>>(
            item_ids, responses, t, adj, item_emb, resp_emb,
            in_a, out_a, b_ih);
        step_gru2<<<BN / 512, 256>>>(
            w_hh, b_hh, w_fc, b_fc, out, t,
            (t == TT - 1) ? h_out : nullptr);
    }
}